// round 15
// baseline (speedup 1.0000x reference)
#include <cuda_runtime.h>
#include <cuda_fp16.h>
#include <cstdint>

#define B_   2048
#define N_   10
#define H_   256
#define LD_  8
#define L_   4
#define FF_  1024
#define NT_  5

typedef __half h16;

// ---------------- scratch -------------------------------------------------------
__device__ float g_h   [B_*N_*H_];
__device__ h16   g_ha  [B_*N_*H_];
__device__ h16   g_qa  [B_*N_*H_];
__device__ h16   g_oa  [B_*N_*H_];
__device__ h16   g_ya  [B_*N_*H_];
__device__ h16   g_f1a [B_*N_*FF_];
__device__ h16   g_h0a [B_*H_];
__device__ float g_ycf [B_*H_];
__device__ h16   g_ctxa[B_*H_];
__device__ float g_kvctx[(size_t)B_*2048];
__device__ float g_kvne [(size_t)128*2048];
__device__ h16   g_neAa[128*H_];
__device__ float g_U   [NT_*N_*H_];
__device__ float g_Vt  [NT_*N_*H_];
__device__ float g_wlat[B_*H_];
// weights (transposed [n][k], single fp16)
__device__ h16 g_wq [L_*65536];
__device__ h16 g_wo [L_*65536];
__device__ h16 g_wkv[L_*131072];
__device__ h16 g_wf1[(size_t)L_*262144];
__device__ h16 g_wf2[(size_t)L_*262144];
__device__ h16 g_wce2[65536];
__device__ float g_bkv[L_*512];

// ---------------- helpers --------------------------------------------------------
__device__ __forceinline__ uint32_t smem_u32(const void* p){
    uint32_t a; asm("{ .reg .u64 t; cvta.to.shared.u64 t, %1; cvt.u32.u64 %0, t; }"
                    : "=r"(a) : "l"(p)); return a;
}
__device__ __forceinline__ void cp16(uint32_t dst, const void* src){
    asm volatile("cp.async.cg.shared.global [%0], [%1], 16;"
                 :: "r"(dst), "l"(__cvta_generic_to_global(src)) : "memory");
}
__device__ __forceinline__ void ldm_x4(uint32_t* r, uint32_t addr){
    asm volatile("ldmatrix.sync.aligned.m8n8.x4.shared.b16 {%0,%1,%2,%3}, [%4];"
        : "=r"(r[0]),"=r"(r[1]),"=r"(r[2]),"=r"(r[3]) : "r"(addr));
}
__device__ __forceinline__ void mma_f16(float* d, const uint32_t* a, const uint32_t* b){
    asm volatile("mma.sync.aligned.m16n8k16.row.col.f32.f16.f16.f32 "
        "{%0,%1,%2,%3}, {%4,%5,%6,%7}, {%8,%9}, {%0,%1,%2,%3};"
        : "+f"(d[0]),"+f"(d[1]),"+f"(d[2]),"+f"(d[3])
        : "r"(a[0]),"r"(a[1]),"r"(a[2]),"r"(a[3]), "r"(b[0]),"r"(b[1]));
}
__device__ __forceinline__ void st_h2(h16* p, size_t idx, float v0, float v1){
    __half2 t; t.x = __float2half_rn(v0); t.y = __float2half_rn(v1);
    *reinterpret_cast<__half2*>(p + idx) = t;
}

// ---------------- merged weight/misc prep ------------------------------------------
__global__ void k_prep(const float* __restrict__ wqkvo,
                       const float* __restrict__ w1, const float* __restrict__ w2,
                       const float* __restrict__ ce_w2,
                       const float* __restrict__ qkvo_b,
                       const float* __restrict__ temb,
                       const float* __restrict__ pemb){
    int idx = blockIdx.x * 256 + threadIdx.x;
    const int QK = L_ * 4 * 65536;           // 1048576
    const int F1 = QK + L_ * 262144;
    const int F2 = F1 + L_ * 262144;
    const int CE = F2 + 65536;
    const int BK = CE + L_ * 512;
    const int NE = BK + 128 * 256;
    if (idx < QK) {
        int mat = idx >> 16, k = (idx >> 8) & 255, n = idx & 255;
        int l = mat >> 2, m = mat & 3;
        h16 h = __float2half_rn(wqkvo[idx]);
        if (m == 0)      g_wq [(size_t)l*65536 + n*256 + k] = h;
        else if (m == 1) g_wkv[(size_t)l*131072 + n*256 + k] = h;
        else if (m == 2) g_wkv[(size_t)l*131072 + (256+n)*256 + k] = h;
        else             g_wo [(size_t)l*65536 + n*256 + k] = h;
    } else if (idx < F1) {
        int j = idx - QK;
        int l = j >> 18, rem = j & 262143, k = rem >> 10, n = rem & 1023;
        g_wf1[(size_t)l*262144 + (size_t)n*256 + k] = __float2half_rn(w1[j]);
    } else if (idx < F2) {
        int j = idx - F1;
        int l = j >> 18, rem = j & 262143, k = rem >> 8, n = rem & 255;
        g_wf2[(size_t)l*262144 + (size_t)n*1024 + k] = __float2half_rn(w2[j]);
    } else if (idx < CE) {
        int j = idx - F2;
        int k = j >> 8, n = j & 255;
        g_wce2[n*256 + k] = __float2half_rn(ce_w2[j]);
    } else if (idx < BK) {
        int j = idx - CE;
        int l = j >> 9, c = j & 511;
        g_bkv[j] = (c < 256) ? qkvo_b[(l*4+1)*256 + c] : qkvo_b[(l*4+2)*256 + (c-256)];
    } else if (idx < NE) {
        int j = idx - BK;
        int row = j >> 8, c = j & 255;
        float v = 0.f;
        if (row < NT_*N_) { int t = row / N_, p = row % N_; v = temb[t*256+c] + pemb[p*256+c]; }
        g_neAa[j] = __float2half_rn(v);
    }
}

// ---- 128-thread 64x64 GEMM: fp16 x fp16, K-chunk 64, 2 stages, 1 barrier/chunk ----
#define ASTRIDE 72
#define SARR 9216
#define STG  18432
#define NS   2

__global__ __launch_bounds__(128, 5)
void k_gemm(const h16* __restrict__ Aa, const h16* __restrict__ Bb,
            const float* __restrict__ bias,
            float* __restrict__ Cf, h16* __restrict__ Ca,
            int M, int N, int K, int relu)
{
    extern __shared__ char smem[];
    const uint32_t sb = smem_u32(smem);
    const int tid = threadIdx.x;
    const int wid = tid >> 5, lane = tid & 31;
    const int warp_m = wid & 1, warp_n = wid >> 1;
    const int bm = blockIdx.y * 64, bn = blockIdx.x * 64;

    float acc[2][4][4];
    #pragma unroll
    for (int i = 0; i < 2; i++)
        #pragma unroll
        for (int j = 0; j < 4; j++)
            #pragma unroll
            for (int q = 0; q < 4; q++) acc[i][j][q] = 0.f;

    const int sub  = lane >> 3;
    const int a_r  = (lane & 7) + ((sub & 1) << 3);
    const int a_kc = (sub >> 1) << 3;
    const int b_n  = (lane & 7) + ((sub >> 1) << 3);
    const int b_kc = (sub & 1) << 3;

    const int nc = K >> 6;

#define STAGE_LOAD(c, s) do {                                                  \
    const int k0_ = (c) * 64;                                                  \
    const uint32_t st_ = sb + (s) * STG;                                       \
    _Pragma("unroll")                                                          \
    for (int i_ = 0; i_ < 8; i_++) {                                           \
        int id_ = i_ * 128 + tid;                                              \
        int arr_ = id_ >> 9;                                                   \
        int rem_ = id_ & 511;                                                  \
        int row_ = rem_ >> 3, ch_ = rem_ & 7;                                  \
        const h16* sp_ = (arr_ == 0)                                           \
            ? Aa + (size_t)(bm + row_) * K + k0_ + ch_ * 8                     \
            : Bb + (size_t)(bn + row_) * K + k0_ + ch_ * 8;                    \
        cp16(st_ + arr_ * SARR + (uint32_t)(row_ * ASTRIDE + ch_ * 8) * 2, sp_);\
    }                                                                          \
} while (0)

    STAGE_LOAD(0, 0);
    asm volatile("cp.async.commit_group;" ::: "memory");

    for (int c = 0; c < nc; c++) {
        const int s = c & 1;
        asm volatile("cp.async.wait_group 0;" ::: "memory");
        __syncthreads();
        if (c + 1 < nc) {
            STAGE_LOAD(c + 1, s ^ 1);
            asm volatile("cp.async.commit_group;" ::: "memory");
        }

        const uint32_t aa_b = sb + s * STG;
        const uint32_t bb_b = aa_b + SARR;

        #pragma unroll
        for (int ks = 0; ks < 4; ks++) {
            uint32_t af[2][4];
            #pragma unroll
            for (int mt = 0; mt < 2; mt++) {
                int rr = warp_m * 32 + mt * 16 + a_r;
                int kc = ks * 16 + a_kc;
                ldm_x4(af[mt], aa_b + (uint32_t)(rr * ASTRIDE + kc) * 2);
            }
            #pragma unroll
            for (int np = 0; np < 2; np++) {
                int nr = warp_n * 32 + np * 16 + b_n;
                int kc = ks * 16 + b_kc;
                uint32_t bw[4];
                ldm_x4(bw, bb_b + (uint32_t)(nr * ASTRIDE + kc) * 2);
                #pragma unroll
                for (int mt = 0; mt < 2; mt++)
                    #pragma unroll
                    for (int nt = 0; nt < 2; nt++)
                        mma_f16(acc[mt][np * 2 + nt], af[mt], bw + nt * 2);
            }
        }
    }

    #pragma unroll
    for (int mt = 0; mt < 2; mt++) {
        int row0 = bm + warp_m * 32 + mt * 16 + (lane >> 2);
        #pragma unroll
        for (int np = 0; np < 2; np++) {
            #pragma unroll
            for (int nt = 0; nt < 2; nt++) {
                int col = bn + warp_n * 32 + np * 16 + nt * 8 + 2 * (lane & 3);
                float b0 = bias[col], b1 = bias[col + 1];
                const float* d = acc[mt][np * 2 + nt];
                float v0 = d[0] + b0, v1 = d[1] + b1;
                float v2 = d[2] + b0, v3 = d[3] + b1;
                if (relu) {
                    v0 = fmaxf(v0, 0.f); v1 = fmaxf(v1, 0.f);
                    v2 = fmaxf(v2, 0.f); v3 = fmaxf(v3, 0.f);
                }
                size_t i0 = (size_t)row0 * N + col;
                size_t i1 = (size_t)(row0 + 8) * N + col;
                if (Cf) {
                    *reinterpret_cast<float2*>(Cf + i0) = make_float2(v0, v1);
                    *reinterpret_cast<float2*>(Cf + i1) = make_float2(v2, v3);
                }
                if (Ca) {
                    st_h2(Ca, i0, v0, v1);
                    st_h2(Ca, i1, v2, v3);
                }
            }
        }
    }
}

// ---------------- small kernels ------------------------------------------------------
__device__ __forceinline__ float2 block_meanvar_256(float x, float* sbuf)
{
    float s = x, s2 = x * x;
    #pragma unroll
    for (int o = 16; o; o >>= 1) {
        s  += __shfl_xor_sync(0xffffffffu, s,  o);
        s2 += __shfl_xor_sync(0xffffffffu, s2, o);
    }
    int w = threadIdx.x >> 5;
    if ((threadIdx.x & 31) == 0) { sbuf[w] = s; sbuf[8 + w] = s2; }
    __syncthreads();
    float ts = 0.f, ts2 = 0.f;
    #pragma unroll
    for (int i = 0; i < 8; i++) { ts += sbuf[i]; ts2 += sbuf[8 + i]; }
    __syncthreads();
    float mean = ts * (1.f / 256.f);
    float var  = ts2 * (1.f / 256.f) - mean * mean;
    return make_float2(mean, rsqrtf(var + 1e-5f));
}

__global__ void k_ctx1(
    const float* __restrict__ lat,
    const float* __restrict__ w1, const float* __restrict__ b1,
    const float* __restrict__ g1, const float* __restrict__ be1,
    const float* __restrict__ ncw1, const float* __restrict__ ncb1,
    const float* __restrict__ ncw2, const float* __restrict__ ncb2,
    const float* __restrict__ ew1, const float* __restrict__ eb1,
    float* __restrict__ out_nc)
{
    int b = blockIdx.x, t = threadIdx.x;
    __shared__ float sl[8];
    __shared__ float sred[16];
    __shared__ float snc[64];
    if (t < 8) sl[t] = lat[b * LD_ + t];
    __syncthreads();

    float x = b1[t];
    #pragma unroll
    for (int k = 0; k < 8; k++) x += sl[k] * w1[k * H_ + t];
    float2 mv = block_meanvar_256(x, sred);
    float h0 = fmaxf((x - mv.x) * mv.y * g1[t] + be1[t], 0.f);
    g_h0a[(size_t)b * H_ + t] = __float2half_rn(h0);

    float a = eb1[t];
    #pragma unroll
    for (int k = 0; k < 8; k++) a += sl[k] * ew1[(2 * H_ + k) * H_ + t];
    g_wlat[(size_t)b * H_ + t] = a;

    if (t < 64) snc[t] = fmaxf(sl[0] * ncw1[t] + sl[1] * ncw1[64 + t] + ncb1[t], 0.f);
    __syncthreads();
    if (t < 3) {
        float o = ncb2[t];
        #pragma unroll
        for (int k = 0; k < 64; k++) o += snc[k] * ncw2[k * 3 + t];
        out_nc[b * 3 + t] = o;
    }
}

__global__ void k_ctx2(const float* __restrict__ pemb,
                       const float* __restrict__ g2, const float* __restrict__ be2)
{
    int b = blockIdx.x, t = threadIdx.x;
    __shared__ float sred[16];
    float y = g_ycf[(size_t)b * H_ + t];
    float2 mv = block_meanvar_256(y, sred);
    float ctx = (y - mv.x) * mv.y * g2[t] + be2[t];
    g_ctxa[(size_t)b * H_ + t] = __float2half_rn(ctx);
    #pragma unroll
    for (int i = 0; i < N_; i++) {
        float hv = ctx + pemb[i * H_ + t];
        size_t idx = ((size_t)b * N_ + i) * H_ + t;
        g_h[idx] = hv;
        g_ha[idx] = __float2half_rn(hv);
    }
}

__global__ void k_attn(int l, const int* __restrict__ types)
{
    int b = blockIdx.x;
    int h = threadIdx.x >> 5, d = threadIdx.x & 31;
    __shared__ int sty[10];
    if (threadIdx.x < 10) sty[threadIdx.x] = types[b * N_ + threadIdx.x];
    __syncthreads();
    int col = h * 32 + d;
    float Kr[11], Vr[11];
    size_t cb = (size_t)b * 2048 + l * 512 + col;
    Kr[0] = g_kvctx[cb]; Vr[0] = g_kvctx[cb + 256];
    #pragma unroll
    for (int m = 1; m <= 10; m++) {
        int combo = sty[m - 1] * N_ + (m - 1);
        size_t nb = (size_t)combo * 2048 + l * 512 + col;
        Kr[m] = g_kvne[nb]; Vr[m] = g_kvne[nb + 256];
    }
    const float scale = 0.17677669529663687f;
    for (int i = 0; i < N_; i++) {
        float q = __half2float(g_qa[((size_t)b * N_ + i) * H_ + col]);
        float sown = -1e30f;
        for (int m = 0; m <= i; m++) {
            float p = q * Kr[m];
            #pragma unroll
            for (int o = 16; o; o >>= 1) p += __shfl_xor_sync(0xffffffffu, p, o);
            if (d == m) sown = p * scale;
        }
        float mx = sown;
        #pragma unroll
        for (int o = 16; o; o >>= 1) mx = fmaxf(mx, __shfl_xor_sync(0xffffffffu, mx, o));
        float e = (d <= i) ? __expf(sown - mx) : 0.f;
        float den = e;
        #pragma unroll
        for (int o = 16; o; o >>= 1) den += __shfl_xor_sync(0xffffffffu, den, o);
        float oacc = 0.f;
        for (int m = 0; m <= i; m++) {
            float a = __shfl_sync(0xffffffffu, e, m);
            oacc += a * Vr[m];
        }
        g_oa[((size_t)b * N_ + i) * H_ + col] = __float2half_rn(oacc / den);
    }
}

// warp-per-row residual+LN; y is fp16. W!=nullptr -> fuse node head, skip h stores.
__global__ void k_resln_w(const h16* __restrict__ y,
                          const float* __restrict__ g, const float* __restrict__ b,
                          const float* __restrict__ W, const float* __restrict__ bb,
                          float* __restrict__ outNode)
{
    int w = threadIdx.x >> 5, lane = threadIdx.x & 31;
    int row = blockIdx.x * 8 + w;
    size_t base = (size_t)row * H_;
    float v[8];
    float s = 0.f, s2 = 0.f;
    #pragma unroll
    for (int q = 0; q < 8; q++) {
        int e = lane + 32 * q;
        float x = g_h[base + e] + __half2float(y[base + e]);
        v[q] = x; s += x; s2 += x * x;
    }
    #pragma unroll
    for (int o = 16; o; o >>= 1) {
        s  += __shfl_xor_sync(0xffffffffu, s,  o);
        s2 += __shfl_xor_sync(0xffffffffu, s2, o);
    }
    float mean = s * (1.f / 256.f);
    float rstd = rsqrtf(s2 * (1.f / 256.f) - mean * mean + 1e-5f);

    if (W == nullptr) {
        #pragma unroll
        for (int q = 0; q < 8; q++) {
            int e = lane + 32 * q;
            float vv = (v[q] - mean) * rstd * g[e] + b[e];
            g_h[base + e] = vv;
            g_ha[base + e] = __float2half_rn(vv);
        }
    } else {
        float a0 = 0, a1 = 0, a2 = 0, a3 = 0, a4 = 0;
        #pragma unroll
        for (int q = 0; q < 8; q++) {
            int e = lane + 32 * q;
            float vv = (v[q] - mean) * rstd * g[e] + b[e];
            const float* wr = W + e * 5;
            a0 += vv * wr[0]; a1 += vv * wr[1]; a2 += vv * wr[2];
            a3 += vv * wr[3]; a4 += vv * wr[4];
        }
        #pragma unroll
        for (int o = 16; o; o >>= 1) {
            a0 += __shfl_xor_sync(0xffffffffu, a0, o);
            a1 += __shfl_xor_sync(0xffffffffu, a1, o);
            a2 += __shfl_xor_sync(0xffffffffu, a2, o);
            a3 += __shfl_xor_sync(0xffffffffu, a3, o);
            a4 += __shfl_xor_sync(0xffffffffu, a4, o);
        }
        if (lane < 5) {
            float r = (lane == 0) ? a0 : (lane == 1) ? a1 : (lane == 2) ? a2
                     : (lane == 3) ? a3 : a4;
            outNode[(size_t)row * 5 + lane] = r + bb[lane];
        }
    }
}

__global__ void k_edge_uv(const float* __restrict__ temb, const float* __restrict__ pemb,
                          const float* __restrict__ w1)
{
    int tt = blockIdx.x / N_, p = blockIdx.x % N_;
    int j = threadIdx.x;
    __shared__ float ne[256];
    ne[j] = temb[tt * H_ + j] + pemb[p * H_ + j];
    __syncthreads();
    float au = 0.f, av = 0.f;
    for (int k = 0; k < 256; k++) {
        float n = ne[k];
        au += n * w1[k * H_ + j];
        av += n * w1[(256 + k) * H_ + j];
    }
    g_U [blockIdx.x * H_ + j] = au;
    g_Vt[blockIdx.x * H_ + j] = av;
}

__global__ void k_edge(const int* __restrict__ types,
                       const float* __restrict__ W2, const float* __restrict__ b2,
                       float* __restrict__ out)
{
    int b = blockIdx.x, t = threadIdx.x;
    int lane = t & 31, w = t >> 5;
    __shared__ float s_w[256];
    __shared__ float s_W2t[8 * 256];
    __shared__ float s_b2[8];
    __shared__ int   s_ty[10];

    s_w[t] = g_wlat[b * H_ + t];
    #pragma unroll
    for (int c = 0; c < 8; c++) s_W2t[c * 256 + t] = W2[t * 8 + c];
    if (t < 10) s_ty[t] = types[b * N_ + t];
    if (t < 8)  s_b2[t] = b2[t];

    float* eb = out + (size_t)b * (N_ * N_ * 8);
    if (t < 80) { int i = t / 8, c = t % 8; eb[(i * N_ + i) * 8 + c] = 0.f; }
    __syncthreads();

    for (int p = w; p < 45; p += 8) {
        int i = 1, base = 0;
        while (base + i <= p) { base += i; i++; }
        int j = p - base;
        const float* Ui = g_U  + ((size_t)s_ty[i] * N_ + i) * H_;
        const float* Vj = g_Vt + ((size_t)s_ty[j] * N_ + j) * H_;
        float hid[8];
        #pragma unroll
        for (int q = 0; q < 8; q++) {
            int e = lane + 32 * q;
            hid[q] = fmaxf(s_w[e] + Ui[e] + Vj[e], 0.f);
        }
        #pragma unroll
        for (int c = 0; c < 8; c++) {
            float acc = 0.f;
            #pragma unroll
            for (int q = 0; q < 8; q++)
                acc += hid[q] * s_W2t[c * 256 + lane + 32 * q];
            #pragma unroll
            for (int o = 16; o; o >>= 1) acc += __shfl_xor_sync(0xffffffffu, acc, o);
            if (lane == 0) {
                float v = acc + s_b2[c];
                eb[(i * N_ + j) * 8 + c] = v;
                eb[(j * N_ + i) * 8 + c] = v;
            }
        }
    }
}

// ---------------- launcher --------------------------------------------------------
extern "C" void kernel_launch(void* const* d_in, const int* in_sizes, int n_in,
                              void* d_out, int out_size)
{
    (void)in_sizes; (void)n_in; (void)out_size;
    const float* latent  = (const float*)d_in[0];
    const int*   types   = (const int*)  d_in[1];
    const float* ce_w1   = (const float*)d_in[2];
    const float* ce_b1   = (const float*)d_in[3];
    const float* ce_g1   = (const float*)d_in[4];
    const float* ce_be1  = (const float*)d_in[5];
    const float* ce_w2   = (const float*)d_in[6];
    const float* ce_b2   = (const float*)d_in[7];
    const float* ce_g2   = (const float*)d_in[8];
    const float* ce_be2  = (const float*)d_in[9];
    const float* nc_w1   = (const float*)d_in[10];
    const float* nc_b1   = (const float*)d_in[11];
    const float* nc_w2   = (const float*)d_in[12];
    const float* nc_b2   = (const float*)d_in[13];
    const float* type_emb= (const float*)d_in[14];
    const float* pos_emb = (const float*)d_in[15];
    const float* qkvo_w  = (const float*)d_in[16];
    const float* qkvo_b  = (const float*)d_in[17];
    const float* ln_g    = (const float*)d_in[18];
    const float* ln_b    = (const float*)d_in[19];
    const float* ffn_w1  = (const float*)d_in[20];
    const float* ffn_b1  = (const float*)d_in[21];
    const float* ffn_w2  = (const float*)d_in[22];
    const float* ffn_b2  = (const float*)d_in[23];
    const float* out_w   = (const float*)d_in[24];
    const float* out_b   = (const float*)d_in[25];
    const float* edge_w1 = (const float*)d_in[26];
    const float* edge_b1 = (const float*)d_in[27];
    const float* edge_w2 = (const float*)d_in[28];
    const float* edge_b2 = (const float*)d_in[29];

    float* out      = (float*)d_out;
    float* out_node = out;
    float* out_nc   = out + (size_t)B_ * N_ * 5;
    float* out_edge = out + (size_t)B_ * N_ * 5 + B_ * 3;

    float *p_ycf, *p_kvctx, *p_kvne;
    h16 *p_ha, *p_qa, *p_oa, *p_ya, *p_f1a, *p_h0a, *p_ctxa, *p_neAa;
    h16 *p_wq, *p_wo, *p_wkv, *p_wf1, *p_wf2, *p_wce2;
    float *p_bkv;
    cudaGetSymbolAddress((void**)&p_ycf,  g_ycf);
    cudaGetSymbolAddress((void**)&p_kvctx,g_kvctx);
    cudaGetSymbolAddress((void**)&p_kvne, g_kvne);
    cudaGetSymbolAddress((void**)&p_ha,   g_ha);
    cudaGetSymbolAddress((void**)&p_qa,   g_qa);
    cudaGetSymbolAddress((void**)&p_oa,   g_oa);
    cudaGetSymbolAddress((void**)&p_ya,   g_ya);
    cudaGetSymbolAddress((void**)&p_f1a,  g_f1a);
    cudaGetSymbolAddress((void**)&p_h0a,  g_h0a);
    cudaGetSymbolAddress((void**)&p_ctxa, g_ctxa);
    cudaGetSymbolAddress((void**)&p_neAa, g_neAa);
    cudaGetSymbolAddress((void**)&p_wq,   g_wq);
    cudaGetSymbolAddress((void**)&p_wo,   g_wo);
    cudaGetSymbolAddress((void**)&p_wkv,  g_wkv);
    cudaGetSymbolAddress((void**)&p_wf1,  g_wf1);
    cudaGetSymbolAddress((void**)&p_wf2,  g_wf2);
    cudaGetSymbolAddress((void**)&p_wce2, g_wce2);
    cudaGetSymbolAddress((void**)&p_bkv,  g_bkv);

    cudaFuncSetAttribute(k_gemm, cudaFuncAttributeMaxDynamicSharedMemorySize, NS * STG);
    const int SMB = NS * STG;

    const int PREP_ELEMS = L_*4*65536 + 2*L_*262144 + 65536 + L_*512 + 128*256;

    k_prep<<<(PREP_ELEMS + 255) / 256, 256>>>(qkvo_w, ffn_w1, ffn_w2,
                                              ce_w2, qkvo_b, type_emb, pos_emb);
    k_ctx1<<<B_, 256>>>(latent, ce_w1, ce_b1, ce_g1, ce_be1,
                        nc_w1, nc_b1, nc_w2, nc_b2, edge_w1, edge_b1, out_nc);
    k_gemm<<<dim3(4, 32), 128, SMB>>>(p_h0a, p_wce2, ce_b2, p_ycf, nullptr,
                                      2048, 256, 256, 0);
    k_ctx2<<<B_, 256>>>(pos_emb, ce_g2, ce_be2);
    k_gemm<<<dim3(32, 32), 128, SMB>>>(p_ctxa, p_wkv, p_bkv, p_kvctx, nullptr,
                                       2048, 2048, 256, 0);
    k_gemm<<<dim3(32, 2), 128, SMB>>>(p_neAa, p_wkv, p_bkv, p_kvne, nullptr,
                                      128, 2048, 256, 0);
    k_edge_uv<<<NT_ * N_, 256>>>(type_emb, pos_emb, edge_w1);

    const int MQ = B_ * N_;   // 20480
    for (int l = 0; l < L_; l++) {
        k_gemm<<<dim3(4, MQ/64), 128, SMB>>>(
            p_ha, p_wq + (size_t)l*65536,
            qkvo_b + (size_t)(l*4)*H_, nullptr, p_qa, MQ, 256, 256, 0);
        k_attn<<<B_, 256>>>(l, types);
        k_gemm<<<dim3(4, MQ/64), 128, SMB>>>(
            p_oa, p_wo + (size_t)l*65536,
            qkvo_b + (size_t)(l*4+3)*H_, nullptr, p_ya, MQ, 256, 256, 0);
        k_resln_w<<<MQ/8, 256>>>(p_ya, ln_g + (size_t)(l*2)*H_, ln_b + (size_t)(l*2)*H_,
                                 nullptr, nullptr, nullptr);
        k_gemm<<<dim3(16, MQ/64), 128, SMB>>>(
            p_ha, p_wf1 + (size_t)l*262144,
            ffn_b1 + (size_t)l*FF_, nullptr, p_f1a, MQ, 1024, 256, 1);
        k_gemm<<<dim3(4, MQ/64), 128, SMB>>>(
            p_f1a, p_wf2 + (size_t)l*262144,
            ffn_b2 + (size_t)l*H_, nullptr, p_ya, MQ, 256, 1024, 0);
        if (l < L_ - 1) {
            k_resln_w<<<MQ/8, 256>>>(p_ya, ln_g + (size_t)(l*2+1)*H_, ln_b + (size_t)(l*2+1)*H_,
                                     nullptr, nullptr, nullptr);
        } else {
            k_resln_w<<<MQ/8, 256>>>(p_ya, ln_g + (size_t)(l*2+1)*H_, ln_b + (size_t)(l*2+1)*H_,
                                     out_w, out_b, out_node);
        }
    }

    k_edge<<<B_, 256>>>(types, edge_w2, edge_b2, out_edge);
}

// round 16
// speedup vs baseline: 1.0108x; 1.0108x over previous
#include <cuda_runtime.h>
#include <cuda_fp16.h>
#include <cstdint>

#define B_   2048
#define N_   10
#define H_   256
#define LD_  8
#define L_   4
#define FF_  1024
#define NT_  5

typedef __half h16;

// ---------------- scratch -------------------------------------------------------
__device__ float g_h   [B_*N_*H_];
__device__ h16   g_ha  [B_*N_*H_];
__device__ h16   g_qa  [B_*N_*H_];
__device__ h16   g_oa  [B_*N_*H_];
__device__ float g_y   [B_*N_*H_];
__device__ h16   g_f1a [B_*N_*FF_];
__device__ h16   g_h0a [B_*H_];
__device__ float g_ycf [B_*H_];
__device__ h16   g_ctxa[B_*H_];
__device__ float g_kvctx[(size_t)B_*2048];
__device__ float g_kvne [(size_t)128*2048];
__device__ h16   g_neAa[128*H_];
__device__ float g_U   [NT_*N_*H_];
__device__ float g_Vt  [NT_*N_*H_];
__device__ float g_wlat[B_*H_];
// weights (transposed [n][k], single fp16)
__device__ h16 g_wq [L_*65536];
__device__ h16 g_wo [L_*65536];
__device__ h16 g_wkv[L_*131072];
__device__ h16 g_wf1[(size_t)L_*262144];
__device__ h16 g_wf2[(size_t)L_*262144];
__device__ h16 g_wce2[65536];
__device__ float g_bkv[L_*512];

// ---------------- helpers --------------------------------------------------------
__device__ __forceinline__ uint32_t smem_u32(const void* p){
    uint32_t a; asm("{ .reg .u64 t; cvta.to.shared.u64 t, %1; cvt.u32.u64 %0, t; }"
                    : "=r"(a) : "l"(p)); return a;
}
__device__ __forceinline__ void cp16(uint32_t dst, const void* src){
    asm volatile("cp.async.cg.shared.global [%0], [%1], 16;"
                 :: "r"(dst), "l"(__cvta_generic_to_global(src)) : "memory");
}
__device__ __forceinline__ void ldm_x4(uint32_t* r, uint32_t addr){
    asm volatile("ldmatrix.sync.aligned.m8n8.x4.shared.b16 {%0,%1,%2,%3}, [%4];"
        : "=r"(r[0]),"=r"(r[1]),"=r"(r[2]),"=r"(r[3]) : "r"(addr));
}
__device__ __forceinline__ void mma_f16(float* d, const uint32_t* a, const uint32_t* b){
    asm volatile("mma.sync.aligned.m16n8k16.row.col.f32.f16.f16.f32 "
        "{%0,%1,%2,%3}, {%4,%5,%6,%7}, {%8,%9}, {%0,%1,%2,%3};"
        : "+f"(d[0]),"+f"(d[1]),"+f"(d[2]),"+f"(d[3])
        : "r"(a[0]),"r"(a[1]),"r"(a[2]),"r"(a[3]), "r"(b[0]),"r"(b[1]));
}
__device__ __forceinline__ void st_h2(h16* p, size_t idx, float v0, float v1){
    __half2 t; t.x = __float2half_rn(v0); t.y = __float2half_rn(v1);
    *reinterpret_cast<__half2*>(p + idx) = t;
}

// ---------------- merged weight/misc prep ------------------------------------------
__global__ void k_prep(const float* __restrict__ wqkvo,
                       const float* __restrict__ w1, const float* __restrict__ w2,
                       const float* __restrict__ ce_w2,
                       const float* __restrict__ qkvo_b,
                       const float* __restrict__ temb,
                       const float* __restrict__ pemb){
    int idx = blockIdx.x * 256 + threadIdx.x;
    const int QK = L_ * 4 * 65536;
    const int F1 = QK + L_ * 262144;
    const int F2 = F1 + L_ * 262144;
    const int CE = F2 + 65536;
    const int BK = CE + L_ * 512;
    const int NE = BK + 128 * 256;
    if (idx < QK) {
        int mat = idx >> 16, k = (idx >> 8) & 255, n = idx & 255;
        int l = mat >> 2, m = mat & 3;
        h16 h = __float2half_rn(wqkvo[idx]);
        if (m == 0)      g_wq [(size_t)l*65536 + n*256 + k] = h;
        else if (m == 1) g_wkv[(size_t)l*131072 + n*256 + k] = h;
        else if (m == 2) g_wkv[(size_t)l*131072 + (256+n)*256 + k] = h;
        else             g_wo [(size_t)l*65536 + n*256 + k] = h;
    } else if (idx < F1) {
        int j = idx - QK;
        int l = j >> 18, rem = j & 262143, k = rem >> 10, n = rem & 1023;
        g_wf1[(size_t)l*262144 + (size_t)n*256 + k] = __float2half_rn(w1[j]);
    } else if (idx < F2) {
        int j = idx - F1;
        int l = j >> 18, rem = j & 262143, k = rem >> 8, n = rem & 255;
        g_wf2[(size_t)l*262144 + (size_t)n*1024 + k] = __float2half_rn(w2[j]);
    } else if (idx < CE) {
        int j = idx - F2;
        int k = j >> 8, n = j & 255;
        g_wce2[n*256 + k] = __float2half_rn(ce_w2[j]);
    } else if (idx < BK) {
        int j = idx - CE;
        int l = j >> 9, c = j & 511;
        g_bkv[j] = (c < 256) ? qkvo_b[(l*4+1)*256 + c] : qkvo_b[(l*4+2)*256 + (c-256)];
    } else if (idx < NE) {
        int j = idx - BK;
        int row = j >> 8, c = j & 255;
        float v = 0.f;
        if (row < NT_*N_) { int t = row / N_, p = row % N_; v = temb[t*256+c] + pemb[p*256+c]; }
        g_neAa[j] = __float2half_rn(v);
    }
}

// ---- 128-thread 64x64 GEMM: fp16 x fp16, K-chunk 64, 2 stages, 1 barrier/chunk ----
#define ASTRIDE 72
#define SARR 9216
#define STG  18432
#define NS   2

__global__ __launch_bounds__(128, 5)
void k_gemm(const h16* __restrict__ Aa, const h16* __restrict__ Bb,
            const float* __restrict__ bias,
            float* __restrict__ Cf, h16* __restrict__ Ca,
            int M, int N, int K, int relu)
{
    extern __shared__ char smem[];
    const uint32_t sb = smem_u32(smem);
    const int tid = threadIdx.x;
    const int wid = tid >> 5, lane = tid & 31;
    const int warp_m = wid & 1, warp_n = wid >> 1;
    const int bm = blockIdx.y * 64, bn = blockIdx.x * 64;

    float acc[2][4][4];
    #pragma unroll
    for (int i = 0; i < 2; i++)
        #pragma unroll
        for (int j = 0; j < 4; j++)
            #pragma unroll
            for (int q = 0; q < 4; q++) acc[i][j][q] = 0.f;

    const int sub  = lane >> 3;
    const int a_r  = (lane & 7) + ((sub & 1) << 3);
    const int a_kc = (sub >> 1) << 3;
    const int b_n  = (lane & 7) + ((sub >> 1) << 3);
    const int b_kc = (sub & 1) << 3;

    const int nc = K >> 6;

#define STAGE_LOAD(c, s) do {                                                  \
    const int k0_ = (c) * 64;                                                  \
    const uint32_t st_ = sb + (s) * STG;                                       \
    _Pragma("unroll")                                                          \
    for (int i_ = 0; i_ < 8; i_++) {                                           \
        int id_ = i_ * 128 + tid;                                              \
        int arr_ = id_ >> 9;                                                   \
        int rem_ = id_ & 511;                                                  \
        int row_ = rem_ >> 3, ch_ = rem_ & 7;                                  \
        const h16* sp_ = (arr_ == 0)                                           \
            ? Aa + (size_t)(bm + row_) * K + k0_ + ch_ * 8                     \
            : Bb + (size_t)(bn + row_) * K + k0_ + ch_ * 8;                    \
        cp16(st_ + arr_ * SARR + (uint32_t)(row_ * ASTRIDE + ch_ * 8) * 2, sp_);\
    }                                                                          \
} while (0)

    STAGE_LOAD(0, 0);
    asm volatile("cp.async.commit_group;" ::: "memory");

    for (int c = 0; c < nc; c++) {
        const int s = c & 1;
        asm volatile("cp.async.wait_group 0;" ::: "memory");
        __syncthreads();
        if (c + 1 < nc) {
            STAGE_LOAD(c + 1, s ^ 1);
            asm volatile("cp.async.commit_group;" ::: "memory");
        }

        const uint32_t aa_b = sb + s * STG;
        const uint32_t bb_b = aa_b + SARR;

        #pragma unroll
        for (int ks = 0; ks < 4; ks++) {
            uint32_t af[2][4];
            #pragma unroll
            for (int mt = 0; mt < 2; mt++) {
                int rr = warp_m * 32 + mt * 16 + a_r;
                int kc = ks * 16 + a_kc;
                ldm_x4(af[mt], aa_b + (uint32_t)(rr * ASTRIDE + kc) * 2);
            }
            #pragma unroll
            for (int np = 0; np < 2; np++) {
                int nr = warp_n * 32 + np * 16 + b_n;
                int kc = ks * 16 + b_kc;
                uint32_t bw[4];
                ldm_x4(bw, bb_b + (uint32_t)(nr * ASTRIDE + kc) * 2);
                #pragma unroll
                for (int mt = 0; mt < 2; mt++)
                    #pragma unroll
                    for (int nt = 0; nt < 2; nt++)
                        mma_f16(acc[mt][np * 2 + nt], af[mt], bw + nt * 2);
            }
        }
    }

    #pragma unroll
    for (int mt = 0; mt < 2; mt++) {
        int row0 = bm + warp_m * 32 + mt * 16 + (lane >> 2);
        #pragma unroll
        for (int np = 0; np < 2; np++) {
            #pragma unroll
            for (int nt = 0; nt < 2; nt++) {
                int col = bn + warp_n * 32 + np * 16 + nt * 8 + 2 * (lane & 3);
                float b0 = bias[col], b1 = bias[col + 1];
                const float* d = acc[mt][np * 2 + nt];
                float v0 = d[0] + b0, v1 = d[1] + b1;
                float v2 = d[2] + b0, v3 = d[3] + b1;
                if (relu) {
                    v0 = fmaxf(v0, 0.f); v1 = fmaxf(v1, 0.f);
                    v2 = fmaxf(v2, 0.f); v3 = fmaxf(v3, 0.f);
                }
                size_t i0 = (size_t)row0 * N + col;
                size_t i1 = (size_t)(row0 + 8) * N + col;
                if (Cf) {
                    *reinterpret_cast<float2*>(Cf + i0) = make_float2(v0, v1);
                    *reinterpret_cast<float2*>(Cf + i1) = make_float2(v2, v3);
                }
                if (Ca) {
                    st_h2(Ca, i0, v0, v1);
                    st_h2(Ca, i1, v2, v3);
                }
            }
        }
    }
}

// ---------------- small kernels ------------------------------------------------------
__device__ __forceinline__ float2 block_meanvar_256(float x, float* sbuf)
{
    float s = x, s2 = x * x;
    #pragma unroll
    for (int o = 16; o; o >>= 1) {
        s  += __shfl_xor_sync(0xffffffffu, s,  o);
        s2 += __shfl_xor_sync(0xffffffffu, s2, o);
    }
    int w = threadIdx.x >> 5;
    if ((threadIdx.x & 31) == 0) { sbuf[w] = s; sbuf[8 + w] = s2; }
    __syncthreads();
    float ts = 0.f, ts2 = 0.f;
    #pragma unroll
    for (int i = 0; i < 8; i++) { ts += sbuf[i]; ts2 += sbuf[8 + i]; }
    __syncthreads();
    float mean = ts * (1.f / 256.f);
    float var  = ts2 * (1.f / 256.f) - mean * mean;
    return make_float2(mean, rsqrtf(var + 1e-5f));
}

__global__ void k_ctx1(
    const float* __restrict__ lat,
    const float* __restrict__ w1, const float* __restrict__ b1,
    const float* __restrict__ g1, const float* __restrict__ be1,
    const float* __restrict__ ncw1, const float* __restrict__ ncb1,
    const float* __restrict__ ncw2, const float* __restrict__ ncb2,
    const float* __restrict__ ew1, const float* __restrict__ eb1,
    float* __restrict__ out_nc)
{
    int b = blockIdx.x, t = threadIdx.x;
    __shared__ float sl[8];
    __shared__ float sred[16];
    __shared__ float snc[64];
    if (t < 8) sl[t] = lat[b * LD_ + t];
    __syncthreads();

    float x = b1[t];
    #pragma unroll
    for (int k = 0; k < 8; k++) x += sl[k] * w1[k * H_ + t];
    float2 mv = block_meanvar_256(x, sred);
    float h0 = fmaxf((x - mv.x) * mv.y * g1[t] + be1[t], 0.f);
    g_h0a[(size_t)b * H_ + t] = __float2half_rn(h0);

    float a = eb1[t];
    #pragma unroll
    for (int k = 0; k < 8; k++) a += sl[k] * ew1[(2 * H_ + k) * H_ + t];
    g_wlat[(size_t)b * H_ + t] = a;

    if (t < 64) snc[t] = fmaxf(sl[0] * ncw1[t] + sl[1] * ncw1[64 + t] + ncb1[t], 0.f);
    __syncthreads();
    if (t < 3) {
        float o = ncb2[t];
        #pragma unroll
        for (int k = 0; k < 64; k++) o += snc[k] * ncw2[k * 3 + t];
        out_nc[b * 3 + t] = o;
    }
}

// warp-per-batch ctx2: LN(ycf row) -> ctxa + h/ha broadcast, no block barriers
__global__ void k_ctx2(const float* __restrict__ pemb,
                       const float* __restrict__ g2, const float* __restrict__ be2)
{
    int w = threadIdx.x >> 5, lane = threadIdx.x & 31;
    int b = blockIdx.x * 8 + w;
    size_t base = (size_t)b * H_;
    float v[8];
    float s = 0.f, s2 = 0.f;
    #pragma unroll
    for (int q = 0; q < 8; q++) {
        int e = lane + 32 * q;
        float x = g_ycf[base + e];
        v[q] = x; s += x; s2 += x * x;
    }
    #pragma unroll
    for (int o = 16; o; o >>= 1) {
        s  += __shfl_xor_sync(0xffffffffu, s,  o);
        s2 += __shfl_xor_sync(0xffffffffu, s2, o);
    }
    float mean = s * (1.f / 256.f);
    float rstd = rsqrtf(s2 * (1.f / 256.f) - mean * mean + 1e-5f);
    #pragma unroll
    for (int q = 0; q < 8; q++) {
        int e = lane + 32 * q;
        float ctx = (v[q] - mean) * rstd * g2[e] + be2[e];
        g_ctxa[base + e] = __float2half_rn(ctx);
        #pragma unroll
        for (int i = 0; i < N_; i++) {
            float hv = ctx + pemb[i * H_ + e];
            size_t idx = ((size_t)b * N_ + i) * H_ + e;
            g_h[idx] = hv;
            g_ha[idx] = __float2half_rn(hv);
        }
    }
}

__global__ void k_attn(int l, const int* __restrict__ types)
{
    int b = blockIdx.x;
    int h = threadIdx.x >> 5, d = threadIdx.x & 31;
    __shared__ int sty[10];
    if (threadIdx.x < 10) sty[threadIdx.x] = types[b * N_ + threadIdx.x];
    __syncthreads();
    int col = h * 32 + d;
    float Kr[11], Vr[11];
    size_t cb = (size_t)b * 2048 + l * 512 + col;
    Kr[0] = g_kvctx[cb]; Vr[0] = g_kvctx[cb + 256];
    #pragma unroll
    for (int m = 1; m <= 10; m++) {
        int combo = sty[m - 1] * N_ + (m - 1);
        size_t nb = (size_t)combo * 2048 + l * 512 + col;
        Kr[m] = g_kvne[nb]; Vr[m] = g_kvne[nb + 256];
    }
    const float scale = 0.17677669529663687f;
    for (int i = 0; i < N_; i++) {
        float q = __half2float(g_qa[((size_t)b * N_ + i) * H_ + col]);
        float sown = -1e30f;
        for (int m = 0; m <= i; m++) {
            float p = q * Kr[m];
            #pragma unroll
            for (int o = 16; o; o >>= 1) p += __shfl_xor_sync(0xffffffffu, p, o);
            if (d == m) sown = p * scale;
        }
        float mx = sown;
        #pragma unroll
        for (int o = 16; o; o >>= 1) mx = fmaxf(mx, __shfl_xor_sync(0xffffffffu, mx, o));
        float e = (d <= i) ? __expf(sown - mx) : 0.f;
        float den = e;
        #pragma unroll
        for (int o = 16; o; o >>= 1) den += __shfl_xor_sync(0xffffffffu, den, o);
        float oacc = 0.f;
        for (int m = 0; m <= i; m++) {
            float a = __shfl_sync(0xffffffffu, e, m);
            oacc += a * Vr[m];
        }
        g_oa[((size_t)b * N_ + i) * H_ + col] = __float2half_rn(oacc / den);
    }
}

// warp-per-row residual+LN; y fp32. W!=nullptr -> fuse node head, skip h stores.
__global__ void k_resln_w(const float* __restrict__ y,
                          const float* __restrict__ g, const float* __restrict__ b,
                          const float* __restrict__ W, const float* __restrict__ bb,
                          float* __restrict__ outNode)
{
    int w = threadIdx.x >> 5, lane = threadIdx.x & 31;
    int row = blockIdx.x * 8 + w;
    size_t base = (size_t)row * H_;
    float v[8];
    float s = 0.f, s2 = 0.f;
    #pragma unroll
    for (int q = 0; q < 8; q++) {
        int e = lane + 32 * q;
        float x = g_h[base + e] + y[base + e];
        v[q] = x; s += x; s2 += x * x;
    }
    #pragma unroll
    for (int o = 16; o; o >>= 1) {
        s  += __shfl_xor_sync(0xffffffffu, s,  o);
        s2 += __shfl_xor_sync(0xffffffffu, s2, o);
    }
    float mean = s * (1.f / 256.f);
    float rstd = rsqrtf(s2 * (1.f / 256.f) - mean * mean + 1e-5f);

    if (W == nullptr) {
        #pragma unroll
        for (int q = 0; q < 8; q++) {
            int e = lane + 32 * q;
            float vv = (v[q] - mean) * rstd * g[e] + b[e];
            g_h[base + e] = vv;
            g_ha[base + e] = __float2half_rn(vv);
        }
    } else {
        float a0 = 0, a1 = 0, a2 = 0, a3 = 0, a4 = 0;
        #pragma unroll
        for (int q = 0; q < 8; q++) {
            int e = lane + 32 * q;
            float vv = (v[q] - mean) * rstd * g[e] + b[e];
            const float* wr = W + e * 5;
            a0 += vv * wr[0]; a1 += vv * wr[1]; a2 += vv * wr[2];
            a3 += vv * wr[3]; a4 += vv * wr[4];
        }
        #pragma unroll
        for (int o = 16; o; o >>= 1) {
            a0 += __shfl_xor_sync(0xffffffffu, a0, o);
            a1 += __shfl_xor_sync(0xffffffffu, a1, o);
            a2 += __shfl_xor_sync(0xffffffffu, a2, o);
            a3 += __shfl_xor_sync(0xffffffffu, a3, o);
            a4 += __shfl_xor_sync(0xffffffffu, a4, o);
        }
        if (lane < 5) {
            float r = (lane == 0) ? a0 : (lane == 1) ? a1 : (lane == 2) ? a2
                     : (lane == 3) ? a3 : a4;
            outNode[(size_t)row * 5 + lane] = r + bb[lane];
        }
    }
}

__global__ void k_edge_uv(const float* __restrict__ temb, const float* __restrict__ pemb,
                          const float* __restrict__ w1)
{
    int tt = blockIdx.x / N_, p = blockIdx.x % N_;
    int j = threadIdx.x;
    __shared__ float ne[256];
    ne[j] = temb[tt * H_ + j] + pemb[p * H_ + j];
    __syncthreads();
    float au = 0.f, av = 0.f;
    for (int k = 0; k < 256; k++) {
        float n = ne[k];
        au += n * w1[k * H_ + j];
        av += n * w1[(256 + k) * H_ + j];
    }
    g_U [blockIdx.x * H_ + j] = au;
    g_Vt[blockIdx.x * H_ + j] = av;
}

__global__ void k_edge(const int* __restrict__ types,
                       const float* __restrict__ W2, const float* __restrict__ b2,
                       float* __restrict__ out)
{
    int b = blockIdx.x, t = threadIdx.x;
    int lane = t & 31, w = t >> 5;
    __shared__ float s_w[256];
    __shared__ float s_W2t[8 * 256];
    __shared__ float s_b2[8];
    __shared__ int   s_ty[10];

    s_w[t] = g_wlat[b * H_ + t];
    #pragma unroll
    for (int c = 0; c < 8; c++) s_W2t[c * 256 + t] = W2[t * 8 + c];
    if (t < 10) s_ty[t] = types[b * N_ + t];
    if (t < 8)  s_b2[t] = b2[t];

    float* eb = out + (size_t)b * (N_ * N_ * 8);
    if (t < 80) { int i = t / 8, c = t % 8; eb[(i * N_ + i) * 8 + c] = 0.f; }
    __syncthreads();

    for (int p = w; p < 45; p += 8) {
        int i = 1, base = 0;
        while (base + i <= p) { base += i; i++; }
        int j = p - base;
        const float* Ui = g_U  + ((size_t)s_ty[i] * N_ + i) * H_;
        const float* Vj = g_Vt + ((size_t)s_ty[j] * N_ + j) * H_;
        float hid[8];
        #pragma unroll
        for (int q = 0; q < 8; q++) {
            int e = lane + 32 * q;
            hid[q] = fmaxf(s_w[e] + Ui[e] + Vj[e], 0.f);
        }
        #pragma unroll
        for (int c = 0; c < 8; c++) {
            float acc = 0.f;
            #pragma unroll
            for (int q = 0; q < 8; q++)
                acc += hid[q] * s_W2t[c * 256 + lane + 32 * q];
            #pragma unroll
            for (int o = 16; o; o >>= 1) acc += __shfl_xor_sync(0xffffffffu, acc, o);
            if (lane == 0) {
                float v = acc + s_b2[c];
                eb[(i * N_ + j) * 8 + c] = v;
                eb[(j * N_ + i) * 8 + c] = v;
            }
        }
    }
}

// ---------------- launcher --------------------------------------------------------
extern "C" void kernel_launch(void* const* d_in, const int* in_sizes, int n_in,
                              void* d_out, int out_size)
{
    (void)in_sizes; (void)n_in; (void)out_size;
    const float* latent  = (const float*)d_in[0];
    const int*   types   = (const int*)  d_in[1];
    const float* ce_w1   = (const float*)d_in[2];
    const float* ce_b1   = (const float*)d_in[3];
    const float* ce_g1   = (const float*)d_in[4];
    const float* ce_be1  = (const float*)d_in[5];
    const float* ce_w2   = (const float*)d_in[6];
    const float* ce_b2   = (const float*)d_in[7];
    const float* ce_g2   = (const float*)d_in[8];
    const float* ce_be2  = (const float*)d_in[9];
    const float* nc_w1   = (const float*)d_in[10];
    const float* nc_b1   = (const float*)d_in[11];
    const float* nc_w2   = (const float*)d_in[12];
    const float* nc_b2   = (const float*)d_in[13];
    const float* type_emb= (const float*)d_in[14];
    const float* pos_emb = (const float*)d_in[15];
    const float* qkvo_w  = (const float*)d_in[16];
    const float* qkvo_b  = (const float*)d_in[17];
    const float* ln_g    = (const float*)d_in[18];
    const float* ln_b    = (const float*)d_in[19];
    const float* ffn_w1  = (const float*)d_in[20];
    const float* ffn_b1  = (const float*)d_in[21];
    const float* ffn_w2  = (const float*)d_in[22];
    const float* ffn_b2  = (const float*)d_in[23];
    const float* out_w   = (const float*)d_in[24];
    const float* out_b   = (const float*)d_in[25];
    const float* edge_w1 = (const float*)d_in[26];
    const float* edge_b1 = (const float*)d_in[27];
    const float* edge_w2 = (const float*)d_in[28];
    const float* edge_b2 = (const float*)d_in[29];

    float* out      = (float*)d_out;
    float* out_node = out;
    float* out_nc   = out + (size_t)B_ * N_ * 5;
    float* out_edge = out + (size_t)B_ * N_ * 5 + B_ * 3;

    float *p_y, *p_ycf, *p_kvctx, *p_kvne;
    h16 *p_ha, *p_qa, *p_oa, *p_f1a, *p_h0a, *p_ctxa, *p_neAa;
    h16 *p_wq, *p_wo, *p_wkv, *p_wf1, *p_wf2, *p_wce2;
    float *p_bkv;
    cudaGetSymbolAddress((void**)&p_y,    g_y);
    cudaGetSymbolAddress((void**)&p_ycf,  g_ycf);
    cudaGetSymbolAddress((void**)&p_kvctx,g_kvctx);
    cudaGetSymbolAddress((void**)&p_kvne, g_kvne);
    cudaGetSymbolAddress((void**)&p_ha,   g_ha);
    cudaGetSymbolAddress((void**)&p_qa,   g_qa);
    cudaGetSymbolAddress((void**)&p_oa,   g_oa);
    cudaGetSymbolAddress((void**)&p_f1a,  g_f1a);
    cudaGetSymbolAddress((void**)&p_h0a,  g_h0a);
    cudaGetSymbolAddress((void**)&p_ctxa, g_ctxa);
    cudaGetSymbolAddress((void**)&p_neAa, g_neAa);
    cudaGetSymbolAddress((void**)&p_wq,   g_wq);
    cudaGetSymbolAddress((void**)&p_wo,   g_wo);
    cudaGetSymbolAddress((void**)&p_wkv,  g_wkv);
    cudaGetSymbolAddress((void**)&p_wf1,  g_wf1);
    cudaGetSymbolAddress((void**)&p_wf2,  g_wf2);
    cudaGetSymbolAddress((void**)&p_wce2, g_wce2);
    cudaGetSymbolAddress((void**)&p_bkv,  g_bkv);

    cudaFuncSetAttribute(k_gemm, cudaFuncAttributeMaxDynamicSharedMemorySize, NS * STG);
    const int SMB = NS * STG;

    const int PREP_ELEMS = L_*4*65536 + 2*L_*262144 + 65536 + L_*512 + 128*256;

    k_prep<<<(PREP_ELEMS + 255) / 256, 256>>>(qkvo_w, ffn_w1, ffn_w2,
                                              ce_w2, qkvo_b, type_emb, pos_emb);
    k_ctx1<<<B_, 256>>>(latent, ce_w1, ce_b1, ce_g1, ce_be1,
                        nc_w1, nc_b1, nc_w2, nc_b2, edge_w1, edge_b1, out_nc);
    k_gemm<<<dim3(4, 32), 128, SMB>>>(p_h0a, p_wce2, ce_b2, p_ycf, nullptr,
                                      2048, 256, 256, 0);
    k_ctx2<<<B_/8, 256>>>(pos_emb, ce_g2, ce_be2);
    k_gemm<<<dim3(32, 32), 128, SMB>>>(p_ctxa, p_wkv, p_bkv, p_kvctx, nullptr,
                                       2048, 2048, 256, 0);
    k_gemm<<<dim3(32, 2), 128, SMB>>>(p_neAa, p_wkv, p_bkv, p_kvne, nullptr,
                                      128, 2048, 256, 0);
    k_edge_uv<<<NT_ * N_, 256>>>(type_emb, pos_emb, edge_w1);

    const int MQ = B_ * N_;   // 20480
    for (int l = 0; l < L_; l++) {
        k_gemm<<<dim3(4, MQ/64), 128, SMB>>>(
            p_ha, p_wq + (size_t)l*65536,
            qkvo_b + (size_t)(l*4)*H_, nullptr, p_qa, MQ, 256, 256, 0);
        k_attn<<<B_, 256>>>(l, types);
        k_gemm<<<dim3(4, MQ/64), 128, SMB>>>(
            p_oa, p_wo + (size_t)l*65536,
            qkvo_b + (size_t)(l*4+3)*H_, p_y, nullptr, MQ, 256, 256, 0);
        k_resln_w<<<MQ/8, 256>>>(p_y, ln_g + (size_t)(l*2)*H_, ln_b + (size_t)(l*2)*H_,
                                 nullptr, nullptr, nullptr);
        k_gemm<<<dim3(16, MQ/64), 128, SMB>>>(
            p_ha, p_wf1 + (size_t)l*262144,
            ffn_b1 + (size_t)l*FF_, nullptr, p_f1a, MQ, 1024, 256, 1);
        k_gemm<<<dim3(4, MQ/64), 128, SMB>>>(
            p_f1a, p_wf2 + (size_t)l*262144,
            ffn_b2 + (size_t)l*H_, p_y, nullptr, MQ, 256, 1024, 0);
        if (l < L_ - 1) {
            k_resln_w<<<MQ/8, 256>>>(p_y, ln_g + (size_t)(l*2+1)*H_, ln_b + (size_t)(l*2+1)*H_,
                                     nullptr, nullptr, nullptr);
        } else {
            k_resln_w<<<MQ/8, 256>>>(p_y, ln_g + (size_t)(l*2+1)*H_, ln_b + (size_t)(l*2+1)*H_,
                                     out_w, out_b, out_node);
        }
    }

    k_edge<<<B_, 256>>>(types, edge_w2, edge_b2, out_edge);
}

// round 17
// speedup vs baseline: 1.0428x; 1.0316x over previous
#include <cuda_runtime.h>
#include <cuda_fp16.h>
#include <cstdint>

#define B_   2048
#define N_   10
#define H_   256
#define LD_  8
#define L_   4
#define FF_  1024
#define NT_  5

typedef __half h16;

// ---------------- scratch -------------------------------------------------------
__device__ float g_h   [B_*N_*H_];
__device__ h16   g_ha  [B_*N_*H_];
__device__ h16   g_qa  [B_*N_*H_];
__device__ h16   g_oa  [B_*N_*H_];
__device__ float g_y   [B_*N_*H_];
__device__ h16   g_f1a [B_*N_*FF_];
__device__ h16   g_h0a [B_*H_];
__device__ float g_ycf [B_*H_];
__device__ h16   g_ctxa[B_*H_];
__device__ float g_kvctx[(size_t)B_*2048];
__device__ float g_kvne [(size_t)128*2048];
__device__ h16   g_neAa[128*H_];
__device__ float g_U   [NT_*N_*H_];
__device__ float g_Vt  [NT_*N_*H_];
__device__ float g_wlat[B_*H_];
// weights (transposed [n][k], single fp16)
__device__ h16 g_wq [L_*65536];
__device__ h16 g_wo [L_*65536];
__device__ h16 g_wkv[L_*131072];
__device__ h16 g_wf1[(size_t)L_*262144];
__device__ h16 g_wf2[(size_t)L_*262144];
__device__ h16 g_wce2[65536];
__device__ float g_bkv[L_*512];

// ---------------- helpers --------------------------------------------------------
__device__ __forceinline__ uint32_t smem_u32(const void* p){
    uint32_t a; asm("{ .reg .u64 t; cvta.to.shared.u64 t, %1; cvt.u32.u64 %0, t; }"
                    : "=r"(a) : "l"(p)); return a;
}
__device__ __forceinline__ void cp16(uint32_t dst, const void* src){
    asm volatile("cp.async.cg.shared.global [%0], [%1], 16;"
                 :: "r"(dst), "l"(__cvta_generic_to_global(src)) : "memory");
}
__device__ __forceinline__ void ldm_x4(uint32_t* r, uint32_t addr){
    asm volatile("ldmatrix.sync.aligned.m8n8.x4.shared.b16 {%0,%1,%2,%3}, [%4];"
        : "=r"(r[0]),"=r"(r[1]),"=r"(r[2]),"=r"(r[3]) : "r"(addr));
}
__device__ __forceinline__ void mma_f16(float* d, const uint32_t* a, const uint32_t* b){
    asm volatile("mma.sync.aligned.m16n8k16.row.col.f32.f16.f16.f32 "
        "{%0,%1,%2,%3}, {%4,%5,%6,%7}, {%8,%9}, {%0,%1,%2,%3};"
        : "+f"(d[0]),"+f"(d[1]),"+f"(d[2]),"+f"(d[3])
        : "r"(a[0]),"r"(a[1]),"r"(a[2]),"r"(a[3]), "r"(b[0]),"r"(b[1]));
}
__device__ __forceinline__ void st_h2(h16* p, size_t idx, float v0, float v1){
    __half2 t; t.x = __float2half_rn(v0); t.y = __float2half_rn(v1);
    *reinterpret_cast<__half2*>(p + idx) = t;
}

// ---------------- tiled-transpose weight prep --------------------------------------
// 64x64 tile transpose through smem: coalesced reads AND writes.
// Tiles: [0,256) qkvo, [256,512) f1, [512,768) f2, [768,784) ce2, then misc blocks.
__global__ void k_prep(const float* __restrict__ wqkvo,
                       const float* __restrict__ w1, const float* __restrict__ w2,
                       const float* __restrict__ ce_w2,
                       const float* __restrict__ qkvo_b,
                       const float* __restrict__ temb,
                       const float* __restrict__ pemb){
    int bid = blockIdx.x;
    int t = threadIdx.x;
    if (bid < 784) {
        const float* in; h16* outp; int inN, outK, k0, n0;
        if (bid < 256) {                       // qkvo: 16 mats of 256x256
            int mat = bid >> 4, tt = bid & 15;
            int l = mat >> 2, m = mat & 3;
            k0 = (tt >> 2) * 64; n0 = (tt & 3) * 64;
            in = wqkvo + (size_t)mat * 65536; inN = 256; outK = 256;
            if (m == 0)      outp = g_wq  + (size_t)l*65536;
            else if (m == 1) outp = g_wkv + (size_t)l*131072;
            else if (m == 2) outp = g_wkv + (size_t)l*131072 + 65536;
            else             outp = g_wo  + (size_t)l*65536;
        } else if (bid < 512) {                // f1: 4 mats 256x1024
            int tt0 = bid - 256; int l = tt0 >> 6, tt = tt0 & 63;
            k0 = (tt >> 4) * 64; n0 = (tt & 15) * 64;
            in = w1 + (size_t)l*262144; inN = 1024; outK = 256;
            outp = g_wf1 + (size_t)l*262144;
        } else if (bid < 768) {                // f2: 4 mats 1024x256
            int tt0 = bid - 512; int l = tt0 >> 6, tt = tt0 & 63;
            k0 = (tt >> 2) * 64; n0 = (tt & 3) * 64;
            in = w2 + (size_t)l*262144; inN = 256; outK = 1024;
            outp = g_wf2 + (size_t)l*262144;
        } else {                               // ce2: 256x256
            int tt = bid - 768;
            k0 = (tt >> 2) * 64; n0 = (tt & 3) * 64;
            in = ce_w2; inN = 256; outK = 256;
            outp = g_wce2;
        }
        __shared__ h16 st[64 * 72];
        int r = t >> 2, cq = (t & 3) << 4;     // input row, col-chunk of 16
        const float* ip = in + (size_t)(k0 + r) * inN + n0 + cq;
        #pragma unroll
        for (int j = 0; j < 16; j += 4) {
            float4 v = *reinterpret_cast<const float4*>(ip + j);
            int n = cq + j;
            st[(n + 0) * 72 + r] = __float2half_rn(v.x);
            st[(n + 1) * 72 + r] = __float2half_rn(v.y);
            st[(n + 2) * 72 + r] = __float2half_rn(v.z);
            st[(n + 3) * 72 + r] = __float2half_rn(v.w);
        }
        __syncthreads();
        h16* op = outp + (size_t)(n0 + r) * outK + k0 + cq;
        #pragma unroll
        for (int j = 0; j < 16; j += 8)
            *reinterpret_cast<uint4*>(op + j) =
                *reinterpret_cast<const uint4*>(&st[r * 72 + cq + j]);
    } else {
        int j = (bid - 784) * 256 + t;         // < L*512 + 128*256
        if (j < L_ * 512) {
            int l = j >> 9, c = j & 511;
            g_bkv[j] = (c < 256) ? qkvo_b[(l*4+1)*256 + c] : qkvo_b[(l*4+2)*256 + (c-256)];
        } else {
            int q = j - L_ * 512;              // < 128*256
            int row = q >> 8, c = q & 255;
            float v = 0.f;
            if (row < NT_*N_) { int tt = row / N_, p = row % N_; v = temb[tt*256+c] + pemb[p*256+c]; }
            g_neAa[q] = __float2half_rn(v);
        }
    }
}

// ---- 128-thread 64x64 GEMM: fp16 x fp16, K-chunk 64, 2 stages, 6 CTAs/SM ----------
#define ASTRIDE 72
#define SARR 9216
#define STG  18432
#define NS   2

__global__ __launch_bounds__(128, 6)
void k_gemm(const h16* __restrict__ Aa, const h16* __restrict__ Bb,
            const float* __restrict__ bias,
            float* __restrict__ Cf, h16* __restrict__ Ca,
            int M, int N, int K, int relu)
{
    extern __shared__ char smem[];
    const uint32_t sb = smem_u32(smem);
    const int tid = threadIdx.x;
    const int wid = tid >> 5, lane = tid & 31;
    const int warp_m = wid & 1, warp_n = wid >> 1;
    const int bm = blockIdx.y * 64, bn = blockIdx.x * 64;

    float acc[2][4][4];
    #pragma unroll
    for (int i = 0; i < 2; i++)
        #pragma unroll
        for (int j = 0; j < 4; j++)
            #pragma unroll
            for (int q = 0; q < 4; q++) acc[i][j][q] = 0.f;

    const int sub  = lane >> 3;
    const int a_r  = (lane & 7) + ((sub & 1) << 3);
    const int a_kc = (sub >> 1) << 3;
    const int b_n  = (lane & 7) + ((sub >> 1) << 3);
    const int b_kc = (sub & 1) << 3;

    const int nc = K >> 6;

#define STAGE_LOAD(c, s) do {                                                  \
    const int k0_ = (c) * 64;                                                  \
    const uint32_t st_ = sb + (s) * STG;                                       \
    _Pragma("unroll")                                                          \
    for (int i_ = 0; i_ < 8; i_++) {                                           \
        int id_ = i_ * 128 + tid;                                              \
        int arr_ = id_ >> 9;                                                   \
        int rem_ = id_ & 511;                                                  \
        int row_ = rem_ >> 3, ch_ = rem_ & 7;                                  \
        const h16* sp_ = (arr_ == 0)                                           \
            ? Aa + (size_t)(bm + row_) * K + k0_ + ch_ * 8                     \
            : Bb + (size_t)(bn + row_) * K + k0_ + ch_ * 8;                    \
        cp16(st_ + arr_ * SARR + (uint32_t)(row_ * ASTRIDE + ch_ * 8) * 2, sp_);\
    }                                                                          \
} while (0)

    STAGE_LOAD(0, 0);
    asm volatile("cp.async.commit_group;" ::: "memory");

    for (int c = 0; c < nc; c++) {
        const int s = c & 1;
        asm volatile("cp.async.wait_group 0;" ::: "memory");
        __syncthreads();
        if (c + 1 < nc) {
            STAGE_LOAD(c + 1, s ^ 1);
            asm volatile("cp.async.commit_group;" ::: "memory");
        }

        const uint32_t aa_b = sb + s * STG;
        const uint32_t bb_b = aa_b + SARR;

        #pragma unroll
        for (int ks = 0; ks < 4; ks++) {
            uint32_t af[2][4];
            #pragma unroll
            for (int mt = 0; mt < 2; mt++) {
                int rr = warp_m * 32 + mt * 16 + a_r;
                int kc = ks * 16 + a_kc;
                ldm_x4(af[mt], aa_b + (uint32_t)(rr * ASTRIDE + kc) * 2);
            }
            #pragma unroll
            for (int np = 0; np < 2; np++) {
                int nr = warp_n * 32 + np * 16 + b_n;
                int kc = ks * 16 + b_kc;
                uint32_t bw[4];
                ldm_x4(bw, bb_b + (uint32_t)(nr * ASTRIDE + kc) * 2);
                #pragma unroll
                for (int mt = 0; mt < 2; mt++)
                    #pragma unroll
                    for (int nt = 0; nt < 2; nt++)
                        mma_f16(acc[mt][np * 2 + nt], af[mt], bw + nt * 2);
            }
        }
    }

    #pragma unroll
    for (int mt = 0; mt < 2; mt++) {
        int row0 = bm + warp_m * 32 + mt * 16 + (lane >> 2);
        #pragma unroll
        for (int np = 0; np < 2; np++) {
            #pragma unroll
            for (int nt = 0; nt < 2; nt++) {
                int col = bn + warp_n * 32 + np * 16 + nt * 8 + 2 * (lane & 3);
                float b0 = bias[col], b1 = bias[col + 1];
                const float* d = acc[mt][np * 2 + nt];
                float v0 = d[0] + b0, v1 = d[1] + b1;
                float v2 = d[2] + b0, v3 = d[3] + b1;
                if (relu) {
                    v0 = fmaxf(v0, 0.f); v1 = fmaxf(v1, 0.f);
                    v2 = fmaxf(v2, 0.f); v3 = fmaxf(v3, 0.f);
                }
                size_t i0 = (size_t)row0 * N + col;
                size_t i1 = (size_t)(row0 + 8) * N + col;
                if (Cf) {
                    *reinterpret_cast<float2*>(Cf + i0) = make_float2(v0, v1);
                    *reinterpret_cast<float2*>(Cf + i1) = make_float2(v2, v3);
                }
                if (Ca) {
                    st_h2(Ca, i0, v0, v1);
                    st_h2(Ca, i1, v2, v3);
                }
            }
        }
    }
}

// ---------------- small kernels ------------------------------------------------------
__device__ __forceinline__ float2 block_meanvar_256(float x, float* sbuf)
{
    float s = x, s2 = x * x;
    #pragma unroll
    for (int o = 16; o; o >>= 1) {
        s  += __shfl_xor_sync(0xffffffffu, s,  o);
        s2 += __shfl_xor_sync(0xffffffffu, s2, o);
    }
    int w = threadIdx.x >> 5;
    if ((threadIdx.x & 31) == 0) { sbuf[w] = s; sbuf[8 + w] = s2; }
    __syncthreads();
    float ts = 0.f, ts2 = 0.f;
    #pragma unroll
    for (int i = 0; i < 8; i++) { ts += sbuf[i]; ts2 += sbuf[8 + i]; }
    __syncthreads();
    float mean = ts * (1.f / 256.f);
    float var  = ts2 * (1.f / 256.f) - mean * mean;
    return make_float2(mean, rsqrtf(var + 1e-5f));
}

__global__ void k_ctx1(
    const float* __restrict__ lat,
    const float* __restrict__ w1, const float* __restrict__ b1,
    const float* __restrict__ g1, const float* __restrict__ be1,
    const float* __restrict__ ncw1, const float* __restrict__ ncb1,
    const float* __restrict__ ncw2, const float* __restrict__ ncb2,
    const float* __restrict__ ew1, const float* __restrict__ eb1,
    float* __restrict__ out_nc)
{
    int b = blockIdx.x, t = threadIdx.x;
    __shared__ float sl[8];
    __shared__ float sred[16];
    __shared__ float snc[64];
    if (t < 8) sl[t] = lat[b * LD_ + t];
    __syncthreads();

    float x = b1[t];
    #pragma unroll
    for (int k = 0; k < 8; k++) x += sl[k] * w1[k * H_ + t];
    float2 mv = block_meanvar_256(x, sred);
    float h0 = fmaxf((x - mv.x) * mv.y * g1[t] + be1[t], 0.f);
    g_h0a[(size_t)b * H_ + t] = __float2half_rn(h0);

    float a = eb1[t];
    #pragma unroll
    for (int k = 0; k < 8; k++) a += sl[k] * ew1[(2 * H_ + k) * H_ + t];
    g_wlat[(size_t)b * H_ + t] = a;

    if (t < 64) snc[t] = fmaxf(sl[0] * ncw1[t] + sl[1] * ncw1[64 + t] + ncb1[t], 0.f);
    __syncthreads();
    if (t < 3) {
        float o = ncb2[t];
        #pragma unroll
        for (int k = 0; k < 64; k++) o += snc[k] * ncw2[k * 3 + t];
        out_nc[b * 3 + t] = o;
    }
}

// warp-per-batch ctx2
__global__ void k_ctx2(const float* __restrict__ pemb,
                       const float* __restrict__ g2, const float* __restrict__ be2)
{
    int w = threadIdx.x >> 5, lane = threadIdx.x & 31;
    int b = blockIdx.x * 8 + w;
    size_t base = (size_t)b * H_;
    float v[8];
    float s = 0.f, s2 = 0.f;
    #pragma unroll
    for (int q = 0; q < 8; q++) {
        int e = lane + 32 * q;
        float x = g_ycf[base + e];
        v[q] = x; s += x; s2 += x * x;
    }
    #pragma unroll
    for (int o = 16; o; o >>= 1) {
        s  += __shfl_xor_sync(0xffffffffu, s,  o);
        s2 += __shfl_xor_sync(0xffffffffu, s2, o);
    }
    float mean = s * (1.f / 256.f);
    float rstd = rsqrtf(s2 * (1.f / 256.f) - mean * mean + 1e-5f);
    #pragma unroll
    for (int q = 0; q < 8; q++) {
        int e = lane + 32 * q;
        float ctx = (v[q] - mean) * rstd * g2[e] + be2[e];
        g_ctxa[base + e] = __float2half_rn(ctx);
        #pragma unroll
        for (int i = 0; i < N_; i++) {
            float hv = ctx + pemb[i * H_ + e];
            size_t idx = ((size_t)b * N_ + i) * H_ + e;
            g_h[idx] = hv;
            g_ha[idx] = __float2half_rn(hv);
        }
    }
}

__global__ void k_attn(int l, const int* __restrict__ types)
{
    int b = blockIdx.x;
    int h = threadIdx.x >> 5, d = threadIdx.x & 31;
    __shared__ int sty[10];
    if (threadIdx.x < 10) sty[threadIdx.x] = types[b * N_ + threadIdx.x];
    __syncthreads();
    int col = h * 32 + d;
    float Kr[11], Vr[11];
    size_t cb = (size_t)b * 2048 + l * 512 + col;
    Kr[0] = g_kvctx[cb]; Vr[0] = g_kvctx[cb + 256];
    #pragma unroll
    for (int m = 1; m <= 10; m++) {
        int combo = sty[m - 1] * N_ + (m - 1);
        size_t nb = (size_t)combo * 2048 + l * 512 + col;
        Kr[m] = g_kvne[nb]; Vr[m] = g_kvne[nb + 256];
    }
    const float scale = 0.17677669529663687f;
    for (int i = 0; i < N_; i++) {
        float q = __half2float(g_qa[((size_t)b * N_ + i) * H_ + col]);
        float sown = -1e30f;
        for (int m = 0; m <= i; m++) {
            float p = q * Kr[m];
            #pragma unroll
            for (int o = 16; o; o >>= 1) p += __shfl_xor_sync(0xffffffffu, p, o);
            if (d == m) sown = p * scale;
        }
        float mx = sown;
        #pragma unroll
        for (int o = 16; o; o >>= 1) mx = fmaxf(mx, __shfl_xor_sync(0xffffffffu, mx, o));
        float e = (d <= i) ? __expf(sown - mx) : 0.f;
        float den = e;
        #pragma unroll
        for (int o = 16; o; o >>= 1) den += __shfl_xor_sync(0xffffffffu, den, o);
        float oacc = 0.f;
        for (int m = 0; m <= i; m++) {
            float a = __shfl_sync(0xffffffffu, e, m);
            oacc += a * Vr[m];
        }
        g_oa[((size_t)b * N_ + i) * H_ + col] = __float2half_rn(oacc / den);
    }
}

// warp-per-row residual+LN; W!=nullptr -> fuse node head, skip h stores.
__global__ void k_resln_w(const float* __restrict__ y,
                          const float* __restrict__ g, const float* __restrict__ b,
                          const float* __restrict__ W, const float* __restrict__ bb,
                          float* __restrict__ outNode)
{
    int w = threadIdx.x >> 5, lane = threadIdx.x & 31;
    int row = blockIdx.x * 8 + w;
    size_t base = (size_t)row * H_;
    float v[8];
    float s = 0.f, s2 = 0.f;
    #pragma unroll
    for (int q = 0; q < 8; q++) {
        int e = lane + 32 * q;
        float x = g_h[base + e] + y[base + e];
        v[q] = x; s += x; s2 += x * x;
    }
    #pragma unroll
    for (int o = 16; o; o >>= 1) {
        s  += __shfl_xor_sync(0xffffffffu, s,  o);
        s2 += __shfl_xor_sync(0xffffffffu, s2, o);
    }
    float mean = s * (1.f / 256.f);
    float rstd = rsqrtf(s2 * (1.f / 256.f) - mean * mean + 1e-5f);

    if (W == nullptr) {
        #pragma unroll
        for (int q = 0; q < 8; q++) {
            int e = lane + 32 * q;
            float vv = (v[q] - mean) * rstd * g[e] + b[e];
            g_h[base + e] = vv;
            g_ha[base + e] = __float2half_rn(vv);
        }
    } else {
        float a0 = 0, a1 = 0, a2 = 0, a3 = 0, a4 = 0;
        #pragma unroll
        for (int q = 0; q < 8; q++) {
            int e = lane + 32 * q;
            float vv = (v[q] - mean) * rstd * g[e] + b[e];
            const float* wr = W + e * 5;
            a0 += vv * wr[0]; a1 += vv * wr[1]; a2 += vv * wr[2];
            a3 += vv * wr[3]; a4 += vv * wr[4];
        }
        #pragma unroll
        for (int o = 16; o; o >>= 1) {
            a0 += __shfl_xor_sync(0xffffffffu, a0, o);
            a1 += __shfl_xor_sync(0xffffffffu, a1, o);
            a2 += __shfl_xor_sync(0xffffffffu, a2, o);
            a3 += __shfl_xor_sync(0xffffffffu, a3, o);
            a4 += __shfl_xor_sync(0xffffffffu, a4, o);
        }
        if (lane < 5) {
            float r = (lane == 0) ? a0 : (lane == 1) ? a1 : (lane == 2) ? a2
                     : (lane == 3) ? a3 : a4;
            outNode[(size_t)row * 5 + lane] = r + bb[lane];
        }
    }
}

__global__ void k_edge_uv(const float* __restrict__ temb, const float* __restrict__ pemb,
                          const float* __restrict__ w1)
{
    int tt = blockIdx.x / N_, p = blockIdx.x % N_;
    int j = threadIdx.x;
    __shared__ float ne[256];
    ne[j] = temb[tt * H_ + j] + pemb[p * H_ + j];
    __syncthreads();
    float au = 0.f, av = 0.f;
    for (int k = 0; k < 256; k++) {
        float n = ne[k];
        au += n * w1[k * H_ + j];
        av += n * w1[(256 + k) * H_ + j];
    }
    g_U [blockIdx.x * H_ + j] = au;
    g_Vt[blockIdx.x * H_ + j] = av;
}

__global__ void k_edge(const int* __restrict__ types,
                       const float* __restrict__ W2, const float* __restrict__ b2,
                       float* __restrict__ out)
{
    int b = blockIdx.x, t = threadIdx.x;
    int lane = t & 31, w = t >> 5;
    __shared__ float s_w[256];
    __shared__ float s_W2t[8 * 256];
    __shared__ float s_b2[8];
    __shared__ int   s_ty[10];

    s_w[t] = g_wlat[b * H_ + t];
    #pragma unroll
    for (int c = 0; c < 8; c++) s_W2t[c * 256 + t] = W2[t * 8 + c];
    if (t < 10) s_ty[t] = types[b * N_ + t];
    if (t < 8)  s_b2[t] = b2[t];

    float* eb = out + (size_t)b * (N_ * N_ * 8);
    if (t < 80) { int i = t / 8, c = t % 8; eb[(i * N_ + i) * 8 + c] = 0.f; }
    __syncthreads();

    for (int p = w; p < 45; p += 8) {
        int i = 1, base = 0;
        while (base + i <= p) { base += i; i++; }
        int j = p - base;
        const float* Ui = g_U  + ((size_t)s_ty[i] * N_ + i) * H_;
        const float* Vj = g_Vt + ((size_t)s_ty[j] * N_ + j) * H_;
        float hid[8];
        #pragma unroll
        for (int q = 0; q < 8; q++) {
            int e = lane + 32 * q;
            hid[q] = fmaxf(s_w[e] + Ui[e] + Vj[e], 0.f);
        }
        #pragma unroll
        for (int c = 0; c < 8; c++) {
            float acc = 0.f;
            #pragma unroll
            for (int q = 0; q < 8; q++)
                acc += hid[q] * s_W2t[c * 256 + lane + 32 * q];
            #pragma unroll
            for (int o = 16; o; o >>= 1) acc += __shfl_xor_sync(0xffffffffu, acc, o);
            if (lane == 0) {
                float v = acc + s_b2[c];
                eb[(i * N_ + j) * 8 + c] = v;
                eb[(j * N_ + i) * 8 + c] = v;
            }
        }
    }
}

// ---------------- launcher --------------------------------------------------------
extern "C" void kernel_launch(void* const* d_in, const int* in_sizes, int n_in,
                              void* d_out, int out_size)
{
    (void)in_sizes; (void)n_in; (void)out_size;
    const float* latent  = (const float*)d_in[0];
    const int*   types   = (const int*)  d_in[1];
    const float* ce_w1   = (const float*)d_in[2];
    const float* ce_b1   = (const float*)d_in[3];
    const float* ce_g1   = (const float*)d_in[4];
    const float* ce_be1  = (const float*)d_in[5];
    const float* ce_w2   = (const float*)d_in[6];
    const float* ce_b2   = (const float*)d_in[7];
    const float* ce_g2   = (const float*)d_in[8];
    const float* ce_be2  = (const float*)d_in[9];
    const float* nc_w1   = (const float*)d_in[10];
    const float* nc_b1   = (const float*)d_in[11];
    const float* nc_w2   = (const float*)d_in[12];
    const float* nc_b2   = (const float*)d_in[13];
    const float* type_emb= (const float*)d_in[14];
    const float* pos_emb = (const float*)d_in[15];
    const float* qkvo_w  = (const float*)d_in[16];
    const float* qkvo_b  = (const float*)d_in[17];
    const float* ln_g    = (const float*)d_in[18];
    const float* ln_b    = (const float*)d_in[19];
    const float* ffn_w1  = (const float*)d_in[20];
    const float* ffn_b1  = (const float*)d_in[21];
    const float* ffn_w2  = (const float*)d_in[22];
    const float* ffn_b2  = (const float*)d_in[23];
    const float* out_w   = (const float*)d_in[24];
    const float* out_b   = (const float*)d_in[25];
    const float* edge_w1 = (const float*)d_in[26];
    const float* edge_b1 = (const float*)d_in[27];
    const float* edge_w2 = (const float*)d_in[28];
    const float* edge_b2 = (const float*)d_in[29];

    float* out      = (float*)d_out;
    float* out_node = out;
    float* out_nc   = out + (size_t)B_ * N_ * 5;
    float* out_edge = out + (size_t)B_ * N_ * 5 + B_ * 3;

    float *p_y, *p_ycf, *p_kvctx, *p_kvne;
    h16 *p_ha, *p_qa, *p_oa, *p_f1a, *p_h0a, *p_ctxa, *p_neAa;
    h16 *p_wq, *p_wo, *p_wkv, *p_wf1, *p_wf2, *p_wce2;
    float *p_bkv;
    cudaGetSymbolAddress((void**)&p_y,    g_y);
    cudaGetSymbolAddress((void**)&p_ycf,  g_ycf);
    cudaGetSymbolAddress((void**)&p_kvctx,g_kvctx);
    cudaGetSymbolAddress((void**)&p_kvne, g_kvne);
    cudaGetSymbolAddress((void**)&p_ha,   g_ha);
    cudaGetSymbolAddress((void**)&p_qa,   g_qa);
    cudaGetSymbolAddress((void**)&p_oa,   g_oa);
    cudaGetSymbolAddress((void**)&p_f1a,  g_f1a);
    cudaGetSymbolAddress((void**)&p_h0a,  g_h0a);
    cudaGetSymbolAddress((void**)&p_ctxa, g_ctxa);
    cudaGetSymbolAddress((void**)&p_neAa, g_neAa);
    cudaGetSymbolAddress((void**)&p_wq,   g_wq);
    cudaGetSymbolAddress((void**)&p_wo,   g_wo);
    cudaGetSymbolAddress((void**)&p_wkv,  g_wkv);
    cudaGetSymbolAddress((void**)&p_wf1,  g_wf1);
    cudaGetSymbolAddress((void**)&p_wf2,  g_wf2);
    cudaGetSymbolAddress((void**)&p_wce2, g_wce2);
    cudaGetSymbolAddress((void**)&p_bkv,  g_bkv);

    cudaFuncSetAttribute(k_gemm, cudaFuncAttributeMaxDynamicSharedMemorySize, NS * STG);
    const int SMB = NS * STG;

    const int MISC = L_*512 + 128*256;
    const int PREP_BLOCKS = 784 + (MISC + 255) / 256;

    k_prep<<<PREP_BLOCKS, 256>>>(qkvo_w, ffn_w1, ffn_w2,
                                 ce_w2, qkvo_b, type_emb, pos_emb);
    k_ctx1<<<B_, 256>>>(latent, ce_w1, ce_b1, ce_g1, ce_be1,
                        nc_w1, nc_b1, nc_w2, nc_b2, edge_w1, edge_b1, out_nc);
    k_gemm<<<dim3(4, 32), 128, SMB>>>(p_h0a, p_wce2, ce_b2, p_ycf, nullptr,
                                      2048, 256, 256, 0);
    k_ctx2<<<B_/8, 256>>>(pos_emb, ce_g2, ce_be2);
    k_gemm<<<dim3(32, 32), 128, SMB>>>(p_ctxa, p_wkv, p_bkv, p_kvctx, nullptr,
                                       2048, 2048, 256, 0);
    k_gemm<<<dim3(32, 2), 128, SMB>>>(p_neAa, p_wkv, p_bkv, p_kvne, nullptr,
                                      128, 2048, 256, 0);
    k_edge_uv<<<NT_ * N_, 256>>>(type_emb, pos_emb, edge_w1);

    const int MQ = B_ * N_;   // 20480
    for (int l = 0; l < L_; l++) {
        k_gemm<<<dim3(4, MQ/64), 128, SMB>>>(
            p_ha, p_wq + (size_t)l*65536,
            qkvo_b + (size_t)(l*4)*H_, nullptr, p_qa, MQ, 256, 256, 0);
        k_attn<<<B_, 256>>>(l, types);
        k_gemm<<<dim3(4, MQ/64), 128, SMB>>>(
            p_oa, p_wo + (size_t)l*65536,
            qkvo_b + (size_t)(l*4+3)*H_, p_y, nullptr, MQ, 256, 256, 0);
        k_resln_w<<<MQ/8, 256>>>(p_y, ln_g + (size_t)(l*2)*H_, ln_b + (size_t)(l*2)*H_,
                                 nullptr, nullptr, nullptr);
        k_gemm<<<dim3(16, MQ/64), 128, SMB>>>(
            p_ha, p_wf1 + (size_t)l*262144,
            ffn_b1 + (size_t)l*FF_, nullptr, p_f1a, MQ, 1024, 256, 1);
        k_gemm<<<dim3(4, MQ/64), 128, SMB>>>(
            p_f1a, p_wf2 + (size_t)l*262144,
            ffn_b2 + (size_t)l*H_, p_y, nullptr, MQ, 256, 1024, 0);
        if (l < L_ - 1) {
            k_resln_w<<<MQ/8, 256>>>(p_y, ln_g + (size_t)(l*2+1)*H_, ln_b + (size_t)(l*2+1)*H_,
                                     nullptr, nullptr, nullptr);
        } else {
            k_resln_w<<<MQ/8, 256>>>(p_y, ln_g + (size_t)(l*2+1)*H_, ln_b + (size_t)(l*2+1)*H_,
                                     out_w, out_b, out_node);
        }
    }

    k_edge<<<B_, 256>>>(types, edge_w2, edge_b2, out_edge);
}